// round 14
// baseline (speedup 1.0000x reference)
#include <cuda_runtime.h>
#include <cuda_fp16.h>
#include <cstdint>
#include <math.h>

// Problem constants
#define NRAYS   8192
#define TSAMP   128
#define HID     128
#define SHDIM   16
#define RAYEXT  10.0f
#define NTHREADS 256

// ---------------- constant-memory weights (filled by kernel_launch) ----------
__constant__ float cW1[384];
__constant__ float cB1[128];
__constant__ float cB2[128];
__constant__ float cWD[128];
__constant__ float cWC[432];
__constant__ float cBC[4];     // bc0, bc1, bc2, bd

// ---------------- warp-level tensor-core helpers ----------------
__device__ __forceinline__ void ldsm_x4(uint32_t* r, uint32_t addr) {
    asm volatile("ldmatrix.sync.aligned.m8n8.x4.shared.b16 {%0,%1,%2,%3}, [%4];"
        : "=r"(r[0]), "=r"(r[1]), "=r"(r[2]), "=r"(r[3]) : "r"(addr));
}
__device__ __forceinline__ void ldsm_x4_t(uint32_t* r, uint32_t addr) {
    asm volatile("ldmatrix.sync.aligned.m8n8.x4.trans.shared.b16 {%0,%1,%2,%3}, [%4];"
        : "=r"(r[0]), "=r"(r[1]), "=r"(r[2]), "=r"(r[3]) : "r"(addr));
}
__device__ __forceinline__ void mma_f16(float* d, const uint32_t* a,
                                        uint32_t b0, uint32_t b1) {
    asm volatile("mma.sync.aligned.m16n8k16.row.col.f32.f16.f16.f32 "
        "{%0,%1,%2,%3}, {%4,%5,%6,%7}, {%8,%9}, {%0,%1,%2,%3};"
        : "+f"(d[0]), "+f"(d[1]), "+f"(d[2]), "+f"(d[3])
        : "r"(a[0]), "r"(a[1]), "r"(a[2]), "r"(a[3]), "r"(b0), "r"(b1));
}
__device__ __forceinline__ uint32_t smem_u32(const void* p) {
    uint32_t a;
    asm("{ .reg .u64 t; cvta.to.shared.u64 t, %1; cvt.u32.u64 %0, t; }"
        : "=r"(a) : "l"(p));
    return a;
}
__device__ __forceinline__ uint32_t pack_h2(__half a, __half b) {
    __half2 t = __halves2half2(a, b);
    return *reinterpret_cast<uint32_t*>(&t);
}
#define BAR_EPI() asm volatile("bar.sync 1, 128;" ::: "memory")

// ---------------- SMEM layout (per CTA) ----------------
#define TSTRIDE  272
#define OFF_A    0              // fp16 A tile, 128 * 272 = 34816
#define OFF_B    34816          // fp16 B tile, 128 * 272 = 34816
#define OFF_F    69632
// float-region offsets (in floats)
#define F_TS   0       // 2 x 128
#define F_MSK  256     // 2 x 128
#define F_WS   512     // 8
#define F_RED  520     // 16
#define F_RAY  536     // 2 x 8
#define F_HA   552     // 128*4 (heads, col-half 0)
#define F_HB   1064    // 128*4 (heads, col-half 1)
#define F_TOTAL 1576
#define SMEM_BYTES (OFF_F + F_TOTAL * 4)

__device__ __forceinline__ void sh3(float x, float y, float z, float* Y) {
    float x2 = x*x, y2 = y*y, z2 = z*z;
    float xy = x*y, yz = y*z, xz = x*z;
    Y[0]  = 0.282094791773878f;
    Y[1]  = -0.48860251190292f * y;
    Y[2]  = 0.48860251190292f * z;
    Y[3]  = -0.48860251190292f * x;
    Y[4]  = 1.0925484305920792f * xy;
    Y[5]  = -1.0925484305920792f * yz;
    Y[6]  = 0.94617469575756f * z2 - 0.31539156525252f;
    Y[7]  = -1.0925484305920792f * xz;
    Y[8]  = 0.5462742152960396f * (x2 - y2);
    Y[9]  = 0.5900435899266435f * y * (-3.0f * x2 + y2);
    Y[10] = 2.8906114426405538f * xy * z;
    Y[11] = 0.4570457994644658f * y * (1.0f - 5.0f * z2);
    Y[12] = 0.3731763325901154f * z * (5.0f * z2 - 3.0f);
    Y[13] = 0.4570457994644658f * x * (1.0f - 5.0f * z2);
    Y[14] = 1.445305721320277f * z * (x2 - y2);
    Y[15] = 0.5900435899266435f * x * (-x2 + 3.0f * y2);
}

__global__ __launch_bounds__(NTHREADS, 2)
void radiance_kernel(const float* __restrict__ origins,
                     const float* __restrict__ dirs,
                     const float* __restrict__ u,
                     const float* __restrict__ W2,
                     float* __restrict__ out)
{
    extern __shared__ char smc[];
    float* sf   = (float*)(smc + OFF_F);
    float* sTS  = sf + F_TS;
    float* sMSK = sf + F_MSK;
    float* sWS  = sf + F_WS;
    float* sRED = sf + F_RED;
    float* sRAY = sf + F_RAY;
    float* sHA  = sf + F_HA;
    float* sHB  = sf + F_HB;

    const uint32_t sbase = smem_u32(smc);
    const int tid  = threadIdx.x;
    const int wid  = tid >> 5;
    const int lane = tid & 31;

    // ================= one-time staging: W2 -> B fp16 [k][n] =================
    {
        #pragma unroll
        for (int g = 0; g < 16; g++) {
            int idx4 = g * NTHREADS + tid;     // 0..4095 (float4 index)
            int k    = idx4 >> 5;              // 0..127
            int n4   = (idx4 & 31) << 2;       // 0..124
            float4 v = __ldg((const float4*)W2 + idx4);
            uint32_t p0 = pack_h2(__float2half(v.x), __float2half(v.y));
            uint32_t p1 = pack_h2(__float2half(v.z), __float2half(v.w));
            uint32_t off = (uint32_t)(k * TSTRIDE + n4 * 2);
            *(uint2*)(smc + OFF_B + off) = make_uint2(p0, p1);
        }
    }
    __syncthreads();

    // GEMM addressing: warp w owns rows [32*(w>>1), +32) (two 16-row slabs)
    // and col half 64*(w&1).
    const int qw = wid >> 1;           // row block 0..3
    const int ch = wid & 1;            // col half 0/1
    const uint32_t aBase0 = sbase + OFF_A
        + (uint32_t)((qw*32 + (lane & 15)) * TSTRIDE + (lane >> 4) * 16);
    const uint32_t aBase1 = aBase0 + (uint32_t)(16 * TSTRIDE);
    const int gg = lane >> 3, ii = lane & 7;
    const uint32_t bRow = (uint32_t)(((gg & 1)*8 + ii) * TSTRIDE + (gg >> 1) * 16);
    const uint32_t bBase = sbase + OFF_B + bRow + (uint32_t)(ch * 128);

    const int G = gridDim.x;

    // ---- front-end executed by warps 0-3 only: whole ray, 2 rows per lane ----
    auto front_end = [&](int ray, int buf) {
        const float ox = __ldg(origins + 3*ray + 0);
        const float oy = __ldg(origins + 3*ray + 1);
        const float oz = __ldg(origins + 3*ray + 2);
        const float dx = __ldg(dirs + 3*ray + 0);
        const float dy = __ldg(dirs + 3*ray + 1);
        const float dz = __ldg(dirs + 3*ray + 2);

        float i0 = 1.0f/dx, i1 = 1.0f/dy, i2 = 1.0f/dz;
        float a0 = (-1.0f - ox)*i0, b0 = (1.0f - ox)*i0;
        float a1 = (-1.0f - oy)*i1, b1_ = (1.0f - oy)*i1;
        float a2 = (-1.0f - oz)*i2, b2_ = (1.0f - oz)*i2;
        float mn0 = fminf(a0,b0), mx0 = fmaxf(a0,b0);
        float mn1 = fminf(a1,b1_), mx1 = fmaxf(a1,b1_);
        float mn2 = fminf(a2,b2_), mx2 = fmaxf(a2,b2_);
        float tnear = fmaxf(fmaxf(fmaxf(mn0, mn1), mn2), 0.0f);
        float tfar  = fminf(fminf(mx0, mx1), mx2);
        float activef = (tfar > tnear) ? 1.0f : 0.0f;
        float tfar_c = fmaxf(tfar, tnear + 1e-3f);
        float dnorm = sqrtf(dx*dx + dy*dy + dz*dz);

        if (tid == 0) {
            float* rs = sRAY + buf*8;
            rs[0] = tfar_c; rs[1] = dnorm; rs[2] = activef;
            rs[3] = dx; rs[4] = dy; rs[5] = dz;
        }

        const int j0 = (lane >> 4) * 64;
        #pragma unroll
        for (int rr = 0; rr < 2; rr++) {
            int row = wid*32 + (lane & 15) + rr*16;
            float uu = __ldg(u + ray*TSAMP + row);
            float frac = ((float)row + uu) * (1.0f/(float)TSAMP);
            float ts = tnear + (tfar_c - tnear) * frac;
            float px = ox + dx*ts, py = oy + dy*ts, pz = oz + dz*ts;
            bool inb = (fabsf(px) <= 1.0f) && (fabsf(py) <= 1.0f) && (fabsf(pz) <= 1.0f);
            sTS[buf*128 + row] = ts;
            sMSK[buf*128 + row] = (inb && activef != 0.0f) ? 1.0f : 0.0f;

            const uint32_t abase = (uint32_t)(OFF_A + row * TSTRIDE);
            #pragma unroll
            for (int g = 0; g < 8; g++) {
                uint32_t hp[4];
                #pragma unroll
                for (int i = 0; i < 8; i += 4) {
                    int j = j0 + g*8 + i;
                    float4 wa = *(const float4*)(cW1 + j);
                    float4 wb = *(const float4*)(cW1 + 128 + j);
                    float4 wc = *(const float4*)(cW1 + 256 + j);
                    float4 bb = *(const float4*)(cB1 + j);
                    float v0 = fmaxf(fmaf(px, wa.x, fmaf(py, wb.x, fmaf(pz, wc.x, bb.x))), 0.0f);
                    float v1 = fmaxf(fmaf(px, wa.y, fmaf(py, wb.y, fmaf(pz, wc.y, bb.y))), 0.0f);
                    float v2 = fmaxf(fmaf(px, wa.z, fmaf(py, wb.z, fmaf(pz, wc.z, bb.z))), 0.0f);
                    float v3 = fmaxf(fmaf(px, wa.w, fmaf(py, wb.w, fmaf(pz, wc.w, bb.w))), 0.0f);
                    hp[(i >> 1)]     = pack_h2(__float2half(v0), __float2half(v1));
                    hp[(i >> 1) + 1] = pack_h2(__float2half(v2), __float2half(v3));
                }
                *(uint4*)(smc + abase + (uint32_t)((j0 + g*8) * 2)) =
                    make_uint4(hp[0], hp[1], hp[2], hp[3]);
            }
        }
    };

    // prologue: warps 0-3 fill A + TS/MSK/RAY buffer 0 for the first ray
    if (wid < 4) front_end(blockIdx.x, 0);

    int p = 0;
    // ================= persistent loop: 1 ray/iter, warp-specialized tail ======
    for (int r = blockIdx.x; r < NRAYS; r += G) {
        __syncthreads();   // A, TS/MSK/RAY[p] ready

        // ---------- GEMM: 32 rows x 64 cols per warp ----------
        float acc0[8][4], acc1[8][4];
        #pragma unroll
        for (int j = 0; j < 8; j++)
            #pragma unroll
            for (int q = 0; q < 4; q++) { acc0[j][q] = 0.0f; acc1[j][q] = 0.0f; }

        #pragma unroll
        for (int s = 0; s < 8; s++) {
            uint32_t ah0[4], ah1[4];
            ldsm_x4(ah0, aBase0 + s*32);
            ldsm_x4(ah1, aBase1 + s*32);
            #pragma unroll
            for (int jp = 0; jp < 4; jp++) {
                uint32_t bh[4];
                ldsm_x4_t(bh, bBase + s*(16*TSTRIDE) + jp*32);
                mma_f16(acc0[2*jp],     ah0, bh[0], bh[1]);
                mma_f16(acc0[2*jp + 1], ah0, bh[2], bh[3]);
                mma_f16(acc1[2*jp],     ah1, bh[0], bh[1]);
                mma_f16(acc1[2*jp + 1], ah1, bh[2], bh[3]);
            }
        }

        // ---------- fused heads, both slabs in one pass (constant weights) ----
        float s0hd0 = 0.0f, s0hd1 = 0.0f, s0c00 = 0.0f, s0c01 = 0.0f, s0c02 = 0.0f;
        float s0c10 = 0.0f, s0c11 = 0.0f, s0c12 = 0.0f;
        float s1hd0 = 0.0f, s1hd1 = 0.0f, s1c00 = 0.0f, s1c01 = 0.0f, s1c02 = 0.0f;
        float s1c10 = 0.0f, s1c11 = 0.0f, s1c12 = 0.0f;
        const int cbase = ch * 64 + (lane & 3) * 2;
        #pragma unroll
        for (int j = 0; j < 8; j++) {
            int c = cbase + j*8;
            float2 b2v = *(const float2*)(cB2 + c);
            float2 wdv = *(const float2*)(cWD + c);
            float2 wA = *(const float2*)(cWC + 3*c);
            float2 wB = *(const float2*)(cWC + 3*c + 2);
            float2 wC = *(const float2*)(cWC + 3*c + 4);
            float w0x = wA.x, w0y = wA.y, w0z = wB.x;
            float w1x = wB.y, w1y = wC.x, w1z = wC.y;

            float h00 = fmaxf(acc0[j][0] + b2v.x, 0.0f);
            float h01 = fmaxf(acc0[j][1] + b2v.y, 0.0f);
            float h80 = fmaxf(acc0[j][2] + b2v.x, 0.0f);
            float h81 = fmaxf(acc0[j][3] + b2v.y, 0.0f);
            s0hd0 = fmaf(h00, wdv.x, fmaf(h01, wdv.y, s0hd0));
            s0hd1 = fmaf(h80, wdv.x, fmaf(h81, wdv.y, s0hd1));
            s0c00 = fmaf(h00, w0x, fmaf(h01, w1x, s0c00));
            s0c01 = fmaf(h00, w0y, fmaf(h01, w1y, s0c01));
            s0c02 = fmaf(h00, w0z, fmaf(h01, w1z, s0c02));
            s0c10 = fmaf(h80, w0x, fmaf(h81, w1x, s0c10));
            s0c11 = fmaf(h80, w0y, fmaf(h81, w1y, s0c11));
            s0c12 = fmaf(h80, w0z, fmaf(h81, w1z, s0c12));

            float g00 = fmaxf(acc1[j][0] + b2v.x, 0.0f);
            float g01 = fmaxf(acc1[j][1] + b2v.y, 0.0f);
            float g80 = fmaxf(acc1[j][2] + b2v.x, 0.0f);
            float g81 = fmaxf(acc1[j][3] + b2v.y, 0.0f);
            s1hd0 = fmaf(g00, wdv.x, fmaf(g01, wdv.y, s1hd0));
            s1hd1 = fmaf(g80, wdv.x, fmaf(g81, wdv.y, s1hd1));
            s1c00 = fmaf(g00, w0x, fmaf(g01, w1x, s1c00));
            s1c01 = fmaf(g00, w0y, fmaf(g01, w1y, s1c01));
            s1c02 = fmaf(g00, w0z, fmaf(g01, w1z, s1c02));
            s1c10 = fmaf(g80, w0x, fmaf(g81, w1x, s1c10));
            s1c11 = fmaf(g80, w0y, fmaf(g81, w1y, s1c11));
            s1c12 = fmaf(g80, w0z, fmaf(g81, w1z, s1c12));
        }

        #pragma unroll
        for (int o = 1; o <= 2; o <<= 1) {
            s0hd0 += __shfl_xor_sync(0xffffffffu, s0hd0, o);
            s0hd1 += __shfl_xor_sync(0xffffffffu, s0hd1, o);
            s0c00 += __shfl_xor_sync(0xffffffffu, s0c00, o);
            s0c01 += __shfl_xor_sync(0xffffffffu, s0c01, o);
            s0c02 += __shfl_xor_sync(0xffffffffu, s0c02, o);
            s0c10 += __shfl_xor_sync(0xffffffffu, s0c10, o);
            s0c11 += __shfl_xor_sync(0xffffffffu, s0c11, o);
            s0c12 += __shfl_xor_sync(0xffffffffu, s0c12, o);
            s1hd0 += __shfl_xor_sync(0xffffffffu, s1hd0, o);
            s1hd1 += __shfl_xor_sync(0xffffffffu, s1hd1, o);
            s1c00 += __shfl_xor_sync(0xffffffffu, s1c00, o);
            s1c01 += __shfl_xor_sync(0xffffffffu, s1c01, o);
            s1c02 += __shfl_xor_sync(0xffffffffu, s1c02, o);
            s1c10 += __shfl_xor_sync(0xffffffffu, s1c10, o);
            s1c11 += __shfl_xor_sync(0xffffffffu, s1c11, o);
            s1c12 += __shfl_xor_sync(0xffffffffu, s1c12, o);
        }
        if ((lane & 3) == 0) {
            float* dst = ch ? sHB : sHA;
            int row = qw*32 + (lane >> 2);
            *(float4*)(dst + row*4)      = make_float4(s0hd0, s0c00, s0c01, s0c02);
            *(float4*)(dst + (row+8)*4)  = make_float4(s0hd1, s0c10, s0c11, s0c12);
            *(float4*)(dst + (row+16)*4) = make_float4(s1hd0, s1c00, s1c01, s1c02);
            *(float4*)(dst + (row+24)*4) = make_float4(s1hd1, s1c10, s1c11, s1c12);
        }
        __syncthreads();   // heads ready; GEMM done -> A tile is dead

        // ======== WARP-SPECIALIZED TAIL ========
        if (wid < 4) {
            // warps 0-3: front-end for the next ray (overwrites A, fills buf p^1)
            int rn = r + G;
            if (rn < NRAYS) front_end(rn, p ^ 1);
        } else {
            // warps 4-7: epilogue for ray r from buffer p (threads t = 0..127)
            const int t = tid - 128;
            const int ew = wid - 4;
            const float* rs = sRAY + p*8;
            float e_tfar_c = rs[0];
            float e_dnorm = rs[1];
            float edx = rs[3], edy = rs[4], edz = rs[5];

            float4 ha = *(const float4*)(sHA + t*4);
            float4 hb = *(const float4*)(sHB + t*4);
            float accd = ha.x + hb.x;
            float ac0  = ha.y + hb.y;
            float ac1  = ha.z + hb.z;
            float ac2  = ha.w + hb.w;

            float inv_n = 1.0f / e_dnorm;
            float Ysh[16];
            sh3(edx*inv_n, edy*inv_n, edz*inv_n, Ysh);
            #pragma unroll
            for (int q = 0; q < SHDIM; q++) {
                float wq = Ysh[q];
                ac0 = fmaf(wq, cWC[(HID + q)*3 + 0], ac0);
                ac1 = fmaf(wq, cWC[(HID + q)*3 + 1], ac1);
                ac2 = fmaf(wq, cWC[(HID + q)*3 + 2], ac2);
            }
            float zz = accd + cBC[3];
            float sig = fmaxf(zz, 0.0f) + log1pf(expf(-fabsf(zz)));
            float m = sMSK[p*128 + t];
            sig *= m;
            float mc0 = m / (1.0f + expf(-(ac0 + cBC[0])));
            float mc1 = m / (1.0f + expf(-(ac1 + cBC[1])));
            float mc2 = m / (1.0f + expf(-(ac2 + cBC[2])));
            float tsv  = sTS[p*128 + t];
            float tnxt = (t < TSAMP - 1) ? sTS[p*128 + t + 1] : (e_tfar_c * RAYEXT);
            float my_sd = sig * (tnxt - tsv) * e_dnorm;

            // inclusive scan over 128 samples within warps 4-7
            float v = my_sd;
            #pragma unroll
            for (int o = 1; o < 32; o <<= 1) {
                float n = __shfl_up_sync(0xffffffffu, v, o);
                if (lane >= o) v += n;
            }
            if (lane == 31) sWS[ew] = v;
            BAR_EPI();
            float woff = 0.0f;
            #pragma unroll
            for (int q = 0; q < 4; q++) woff += (q < ew) ? sWS[q] : 0.0f;
            float csum = v + woff;

            float wgt = expf(my_sd - csum) - expf(-csum);
            float rc0 = wgt * mc0, rc1 = wgt * mc1, rc2 = wgt * mc2;

            #pragma unroll
            for (int o = 16; o; o >>= 1) {
                rc0 += __shfl_xor_sync(0xffffffffu, rc0, o);
                rc1 += __shfl_xor_sync(0xffffffffu, rc1, o);
                rc2 += __shfl_xor_sync(0xffffffffu, rc2, o);
                wgt += __shfl_xor_sync(0xffffffffu, wgt, o);
            }
            if (lane == 0) {
                *(float4*)(sRED + ew*4) = make_float4(rc0, rc1, rc2, wgt);
            }
            BAR_EPI();
            if (t == 0) {
                float4 q0 = *(const float4*)(sRED + 0);
                float4 q1 = *(const float4*)(sRED + 4);
                float4 q2 = *(const float4*)(sRED + 8);
                float4 q3 = *(const float4*)(sRED + 12);
                float o0 = q0.x + q1.x + q2.x + q3.x;
                float o1 = q0.y + q1.y + q2.y + q3.y;
                float o2 = q0.z + q1.z + q2.z + q3.z;
                float o3 = q0.w + q1.w + q2.w + q3.w;
                bool act = (rs[2] != 0.0f);
                float4 res;
                res.x = act ? o0 : 0.0f;
                res.y = act ? o1 : 0.0f;
                res.z = act ? o2 : 0.0f;
                res.w = act ? o3 : 0.0f;
                *(float4*)(out + (size_t)r*4) = res;
            }
        }
        p ^= 1;
        // loop-top __syncthreads() is the only cross-group barrier
    }
}

extern "C" void kernel_launch(void* const* d_in, const int* in_sizes, int n_in,
                              void* d_out, int out_size) {
    const float* origins = (const float*)d_in[0];
    const float* dirs    = (const float*)d_in[1];
    const float* u       = (const float*)d_in[2];
    const float* W1      = (const float*)d_in[3];
    const float* b1      = (const float*)d_in[4];
    const float* W2      = (const float*)d_in[5];
    const float* b2      = (const float*)d_in[6];
    const float* Wd      = (const float*)d_in[7];
    const float* bd      = (const float*)d_in[8];
    const float* Wc      = (const float*)d_in[9];
    const float* bc      = (const float*)d_in[10];
    float* out = (float*)d_out;

    // Stage small weights into constant memory (async D2D, graph-capturable)
    cudaMemcpyToSymbolAsync(cW1, W1, 384*sizeof(float), 0, cudaMemcpyDeviceToDevice);
    cudaMemcpyToSymbolAsync(cB1, b1, 128*sizeof(float), 0, cudaMemcpyDeviceToDevice);
    cudaMemcpyToSymbolAsync(cB2, b2, 128*sizeof(float), 0, cudaMemcpyDeviceToDevice);
    cudaMemcpyToSymbolAsync(cWD, Wd, 128*sizeof(float), 0, cudaMemcpyDeviceToDevice);
    cudaMemcpyToSymbolAsync(cWC, Wc, 432*sizeof(float), 0, cudaMemcpyDeviceToDevice);
    cudaMemcpyToSymbolAsync(cBC, bc, 3*sizeof(float), 0, cudaMemcpyDeviceToDevice);
    cudaMemcpyToSymbolAsync(cBC, bd, sizeof(float), 3*sizeof(float),
                            cudaMemcpyDeviceToDevice);

    int dev = 0, nsm = 148;
    cudaGetDevice(&dev);
    cudaDeviceGetAttribute(&nsm, cudaDevAttrMultiProcessorCount, dev);

    cudaFuncSetAttribute(radiance_kernel,
                         cudaFuncAttributeMaxDynamicSharedMemorySize, SMEM_BYTES);
    radiance_kernel<<<nsm * 2, NTHREADS, SMEM_BYTES>>>(origins, dirs, u, W2, out);
}

// round 15
// speedup vs baseline: 1.3187x; 1.3187x over previous
#include <cuda_runtime.h>
#include <cuda_fp16.h>
#include <cstdint>
#include <math.h>

// Problem constants
#define NRAYS   8192
#define TSAMP   128
#define HID     128
#define SHDIM   16
#define RAYEXT  10.0f
#define NTHREADS 256

// ---------------- warp-level tensor-core helpers ----------------
__device__ __forceinline__ void ldsm_x4(uint32_t* r, uint32_t addr) {
    asm volatile("ldmatrix.sync.aligned.m8n8.x4.shared.b16 {%0,%1,%2,%3}, [%4];"
        : "=r"(r[0]), "=r"(r[1]), "=r"(r[2]), "=r"(r[3]) : "r"(addr));
}
__device__ __forceinline__ void ldsm_x4_t(uint32_t* r, uint32_t addr) {
    asm volatile("ldmatrix.sync.aligned.m8n8.x4.trans.shared.b16 {%0,%1,%2,%3}, [%4];"
        : "=r"(r[0]), "=r"(r[1]), "=r"(r[2]), "=r"(r[3]) : "r"(addr));
}
__device__ __forceinline__ void mma_f16(float* d, const uint32_t* a,
                                        uint32_t b0, uint32_t b1) {
    asm volatile("mma.sync.aligned.m16n8k16.row.col.f32.f16.f16.f32 "
        "{%0,%1,%2,%3}, {%4,%5,%6,%7}, {%8,%9}, {%0,%1,%2,%3};"
        : "+f"(d[0]), "+f"(d[1]), "+f"(d[2]), "+f"(d[3])
        : "r"(a[0]), "r"(a[1]), "r"(a[2]), "r"(a[3]), "r"(b0), "r"(b1));
}
__device__ __forceinline__ uint32_t smem_u32(const void* p) {
    uint32_t a;
    asm("{ .reg .u64 t; cvta.to.shared.u64 t, %1; cvt.u32.u64 %0, t; }"
        : "=r"(a) : "l"(p));
    return a;
}
__device__ __forceinline__ uint32_t pack_h2(__half a, __half b) {
    __half2 t = __halves2half2(a, b);
    return *reinterpret_cast<uint32_t*>(&t);
}
#define BAR_EPI() asm volatile("bar.sync 1, 128;" ::: "memory")

// ---------------- SMEM layout (per CTA) ----------------
#define TSTRIDE  272
#define OFF_A    0              // fp16 A tile, 128 * 272 = 34816
#define OFF_B    34816          // fp16 B tile, 128 * 272 = 34816
#define OFF_F    69632
// float-region offsets (in floats)
#define F_W1   0       // 384
#define F_B1   384     // 128
#define F_B2   512     // 128
#define F_WD   640     // 128
#define F_WC   768     // 432
#define F_BC   1200    // 4 (bc0,bc1,bc2,bd)
#define F_TS   1216    // 2 x 128
#define F_MSK  1472    // 2 x 128
#define F_WS   1728    // 8
#define F_RED  1744    // 16
#define F_RAY  1760    // 2 x 8
#define F_HA   1776    // 128*4 (heads, col-half 0)
#define F_HB   2288    // 128*4 (heads, col-half 1)
#define F_TOTAL 2800
#define SMEM_BYTES (OFF_F + F_TOTAL * 4)

__device__ __forceinline__ void sh3(float x, float y, float z, float* Y) {
    float x2 = x*x, y2 = y*y, z2 = z*z;
    float xy = x*y, yz = y*z, xz = x*z;
    Y[0]  = 0.282094791773878f;
    Y[1]  = -0.48860251190292f * y;
    Y[2]  = 0.48860251190292f * z;
    Y[3]  = -0.48860251190292f * x;
    Y[4]  = 1.0925484305920792f * xy;
    Y[5]  = -1.0925484305920792f * yz;
    Y[6]  = 0.94617469575756f * z2 - 0.31539156525252f;
    Y[7]  = -1.0925484305920792f * xz;
    Y[8]  = 0.5462742152960396f * (x2 - y2);
    Y[9]  = 0.5900435899266435f * y * (-3.0f * x2 + y2);
    Y[10] = 2.8906114426405538f * xy * z;
    Y[11] = 0.4570457994644658f * y * (1.0f - 5.0f * z2);
    Y[12] = 0.3731763325901154f * z * (5.0f * z2 - 3.0f);
    Y[13] = 0.4570457994644658f * x * (1.0f - 5.0f * z2);
    Y[14] = 1.445305721320277f * z * (x2 - y2);
    Y[15] = 0.5900435899266435f * x * (-x2 + 3.0f * y2);
}

__global__ __launch_bounds__(NTHREADS, 2)
void radiance_kernel(const float* __restrict__ origins,
                     const float* __restrict__ dirs,
                     const float* __restrict__ u,
                     const float* __restrict__ W1,
                     const float* __restrict__ b1,
                     const float* __restrict__ W2,
                     const float* __restrict__ b2,
                     const float* __restrict__ Wd,
                     const float* __restrict__ bd,
                     const float* __restrict__ Wc,
                     const float* __restrict__ bc,
                     float* __restrict__ out)
{
    extern __shared__ char smc[];
    float* sf   = (float*)(smc + OFF_F);
    float* sW1  = sf + F_W1;
    float* sB1  = sf + F_B1;
    float* sB2  = sf + F_B2;
    float* sWD  = sf + F_WD;
    float* sWC  = sf + F_WC;
    float* sBC  = sf + F_BC;
    float* sTS  = sf + F_TS;
    float* sMSK = sf + F_MSK;
    float* sWS  = sf + F_WS;
    float* sRED = sf + F_RED;
    float* sRAY = sf + F_RAY;
    float* sHA  = sf + F_HA;
    float* sHB  = sf + F_HB;

    const uint32_t sbase = smem_u32(smc);
    const int tid  = threadIdx.x;
    const int wid  = tid >> 5;
    const int lane = tid & 31;

    // ================= one-time staging (persistent CTA) =================
    for (int i = tid; i < 384; i += NTHREADS) sW1[i] = W1[i];
    if (tid < 128) {
        sB1[tid] = b1[tid];
        sB2[tid] = b2[tid];
        sWD[tid] = Wd[tid];
    }
    for (int i = tid; i < 432; i += NTHREADS) sWC[i] = Wc[i];
    if (tid < 3) sBC[tid] = bc[tid];
    if (tid == 3) sBC[3] = bd[0];

    // W2 -> B fp16 [k][n] (native layout, coalesced; one static rounding)
    {
        #pragma unroll
        for (int g = 0; g < 16; g++) {
            int idx4 = g * NTHREADS + tid;     // 0..4095 (float4 index)
            int k    = idx4 >> 5;              // 0..127
            int n4   = (idx4 & 31) << 2;       // 0..124
            float4 v = __ldg((const float4*)W2 + idx4);
            uint32_t p0 = pack_h2(__float2half(v.x), __float2half(v.y));
            uint32_t p1 = pack_h2(__float2half(v.z), __float2half(v.w));
            uint32_t off = (uint32_t)(k * TSTRIDE + n4 * 2);
            *(uint2*)(smc + OFF_B + off) = make_uint2(p0, p1);
        }
    }
    __syncthreads();

    // GEMM addressing: warp w owns rows [32*(w>>1), +32) (two 16-row slabs)
    // and col half 64*(w&1).
    const int qw = wid >> 1;           // row block 0..3
    const int ch = wid & 1;            // col half 0/1
    const uint32_t aBase0 = sbase + OFF_A
        + (uint32_t)((qw*32 + (lane & 15)) * TSTRIDE + (lane >> 4) * 16);
    const uint32_t aBase1 = aBase0 + (uint32_t)(16 * TSTRIDE);
    const int gg = lane >> 3, ii = lane & 7;
    const uint32_t bRow = (uint32_t)(((gg & 1)*8 + ii) * TSTRIDE + (gg >> 1) * 16);
    const uint32_t bBase = sbase + OFF_B + bRow + (uint32_t)(ch * 128);

    const int G = gridDim.x;

    // ---- front-end share: each warp fills 16 A-rows (1 row-slot per lane pair)
    // warp w covers rows [w*16, w*16+16); lane&15 selects row, lane>>4 selects
    // k-half. Every thread recomputes ray constants (cheap).
    auto front_end = [&](int ray, int buf) {
        const float ox = __ldg(origins + 3*ray + 0);
        const float oy = __ldg(origins + 3*ray + 1);
        const float oz = __ldg(origins + 3*ray + 2);
        const float dx = __ldg(dirs + 3*ray + 0);
        const float dy = __ldg(dirs + 3*ray + 1);
        const float dz = __ldg(dirs + 3*ray + 2);

        float i0 = 1.0f/dx, i1 = 1.0f/dy, i2 = 1.0f/dz;
        float a0 = (-1.0f - ox)*i0, b0 = (1.0f - ox)*i0;
        float a1 = (-1.0f - oy)*i1, b1_ = (1.0f - oy)*i1;
        float a2 = (-1.0f - oz)*i2, b2_ = (1.0f - oz)*i2;
        float mn0 = fminf(a0,b0), mx0 = fmaxf(a0,b0);
        float mn1 = fminf(a1,b1_), mx1 = fmaxf(a1,b1_);
        float mn2 = fminf(a2,b2_), mx2 = fmaxf(a2,b2_);
        float tnear = fmaxf(fmaxf(fmaxf(mn0, mn1), mn2), 0.0f);
        float tfar  = fminf(fminf(mx0, mx1), mx2);
        float activef = (tfar > tnear) ? 1.0f : 0.0f;
        float tfar_c = fmaxf(tfar, tnear + 1e-3f);
        float dnorm = sqrtf(dx*dx + dy*dy + dz*dz);

        if (tid == 0) {
            float* rs = sRAY + buf*8;
            rs[0] = tfar_c; rs[1] = dnorm; rs[2] = activef;
            rs[3] = dx; rs[4] = dy; rs[5] = dz;
        }

        const int row = wid*16 + (lane & 15);
        const int j0  = (lane >> 4) * 64;

        float uu = __ldg(u + ray*TSAMP + row);
        float frac = ((float)row + uu) * (1.0f/(float)TSAMP);
        float ts = tnear + (tfar_c - tnear) * frac;
        float px = ox + dx*ts, py = oy + dy*ts, pz = oz + dz*ts;
        bool inb = (fabsf(px) <= 1.0f) && (fabsf(py) <= 1.0f) && (fabsf(pz) <= 1.0f);
        sTS[buf*128 + row] = ts;
        sMSK[buf*128 + row] = (inb && activef != 0.0f) ? 1.0f : 0.0f;

        const uint32_t abase = (uint32_t)(OFF_A + row * TSTRIDE);
        #pragma unroll
        for (int g = 0; g < 8; g++) {
            uint32_t hp[4];
            #pragma unroll
            for (int i = 0; i < 8; i += 4) {
                int j = j0 + g*8 + i;
                float4 wa = *(const float4*)(sW1 + j);
                float4 wb = *(const float4*)(sW1 + 128 + j);
                float4 wc = *(const float4*)(sW1 + 256 + j);
                float4 bb = *(const float4*)(sB1 + j);
                float v0 = fmaxf(fmaf(px, wa.x, fmaf(py, wb.x, fmaf(pz, wc.x, bb.x))), 0.0f);
                float v1 = fmaxf(fmaf(px, wa.y, fmaf(py, wb.y, fmaf(pz, wc.y, bb.y))), 0.0f);
                float v2 = fmaxf(fmaf(px, wa.z, fmaf(py, wb.z, fmaf(pz, wc.z, bb.z))), 0.0f);
                float v3 = fmaxf(fmaf(px, wa.w, fmaf(py, wb.w, fmaf(pz, wc.w, bb.w))), 0.0f);
                hp[(i >> 1)]     = pack_h2(__float2half(v0), __float2half(v1));
                hp[(i >> 1) + 1] = pack_h2(__float2half(v2), __float2half(v3));
            }
            *(uint4*)(smc + abase + (uint32_t)((j0 + g*8) * 2)) =
                make_uint4(hp[0], hp[1], hp[2], hp[3]);
        }
    };

    // prologue: all warps fill their FE share for the first ray
    front_end(blockIdx.x, 0);

    int p = 0;
    // ================= persistent loop: 1 ray/iter, balanced specialized tail ==
    for (int r = blockIdx.x; r < NRAYS; r += G) {
        __syncthreads();   // A, TS/MSK/RAY[p] ready

        // ---------- GEMM: 32 rows x 64 cols per warp ----------
        float acc0[8][4], acc1[8][4];
        #pragma unroll
        for (int j = 0; j < 8; j++)
            #pragma unroll
            for (int q = 0; q < 4; q++) { acc0[j][q] = 0.0f; acc1[j][q] = 0.0f; }

        #pragma unroll
        for (int s = 0; s < 8; s++) {
            uint32_t ah0[4], ah1[4];
            ldsm_x4(ah0, aBase0 + s*32);
            ldsm_x4(ah1, aBase1 + s*32);
            #pragma unroll
            for (int jp = 0; jp < 4; jp++) {
                uint32_t bh[4];
                ldsm_x4_t(bh, bBase + s*(16*TSTRIDE) + jp*32);
                mma_f16(acc0[2*jp],     ah0, bh[0], bh[1]);
                mma_f16(acc0[2*jp + 1], ah0, bh[2], bh[3]);
                mma_f16(acc1[2*jp],     ah1, bh[0], bh[1]);
                mma_f16(acc1[2*jp + 1], ah1, bh[2], bh[3]);
            }
        }

        // ---------- fused heads, both slabs in one pass ----------
        float s0hd0 = 0.0f, s0hd1 = 0.0f, s0c00 = 0.0f, s0c01 = 0.0f, s0c02 = 0.0f;
        float s0c10 = 0.0f, s0c11 = 0.0f, s0c12 = 0.0f;
        float s1hd0 = 0.0f, s1hd1 = 0.0f, s1c00 = 0.0f, s1c01 = 0.0f, s1c02 = 0.0f;
        float s1c10 = 0.0f, s1c11 = 0.0f, s1c12 = 0.0f;
        const int cbase = ch * 64 + (lane & 3) * 2;
        #pragma unroll
        for (int j = 0; j < 8; j++) {
            int c = cbase + j*8;
            float2 b2v = *(const float2*)(sB2 + c);
            float2 wdv = *(const float2*)(sWD + c);
            float2 wA = *(const float2*)(sWC + 3*c);
            float2 wB = *(const float2*)(sWC + 3*c + 2);
            float2 wC = *(const float2*)(sWC + 3*c + 4);
            float w0x = wA.x, w0y = wA.y, w0z = wB.x;
            float w1x = wB.y, w1y = wC.x, w1z = wC.y;

            float h00 = fmaxf(acc0[j][0] + b2v.x, 0.0f);
            float h01 = fmaxf(acc0[j][1] + b2v.y, 0.0f);
            float h80 = fmaxf(acc0[j][2] + b2v.x, 0.0f);
            float h81 = fmaxf(acc0[j][3] + b2v.y, 0.0f);
            s0hd0 = fmaf(h00, wdv.x, fmaf(h01, wdv.y, s0hd0));
            s0hd1 = fmaf(h80, wdv.x, fmaf(h81, wdv.y, s0hd1));
            s0c00 = fmaf(h00, w0x, fmaf(h01, w1x, s0c00));
            s0c01 = fmaf(h00, w0y, fmaf(h01, w1y, s0c01));
            s0c02 = fmaf(h00, w0z, fmaf(h01, w1z, s0c02));
            s0c10 = fmaf(h80, w0x, fmaf(h81, w1x, s0c10));
            s0c11 = fmaf(h80, w0y, fmaf(h81, w1y, s0c11));
            s0c12 = fmaf(h80, w0z, fmaf(h81, w1z, s0c12));

            float g00 = fmaxf(acc1[j][0] + b2v.x, 0.0f);
            float g01 = fmaxf(acc1[j][1] + b2v.y, 0.0f);
            float g80 = fmaxf(acc1[j][2] + b2v.x, 0.0f);
            float g81 = fmaxf(acc1[j][3] + b2v.y, 0.0f);
            s1hd0 = fmaf(g00, wdv.x, fmaf(g01, wdv.y, s1hd0));
            s1hd1 = fmaf(g80, wdv.x, fmaf(g81, wdv.y, s1hd1));
            s1c00 = fmaf(g00, w0x, fmaf(g01, w1x, s1c00));
            s1c01 = fmaf(g00, w0y, fmaf(g01, w1y, s1c01));
            s1c02 = fmaf(g00, w0z, fmaf(g01, w1z, s1c02));
            s1c10 = fmaf(g80, w0x, fmaf(g81, w1x, s1c10));
            s1c11 = fmaf(g80, w0y, fmaf(g81, w1y, s1c11));
            s1c12 = fmaf(g80, w0z, fmaf(g81, w1z, s1c12));
        }

        #pragma unroll
        for (int o = 1; o <= 2; o <<= 1) {
            s0hd0 += __shfl_xor_sync(0xffffffffu, s0hd0, o);
            s0hd1 += __shfl_xor_sync(0xffffffffu, s0hd1, o);
            s0c00 += __shfl_xor_sync(0xffffffffu, s0c00, o);
            s0c01 += __shfl_xor_sync(0xffffffffu, s0c01, o);
            s0c02 += __shfl_xor_sync(0xffffffffu, s0c02, o);
            s0c10 += __shfl_xor_sync(0xffffffffu, s0c10, o);
            s0c11 += __shfl_xor_sync(0xffffffffu, s0c11, o);
            s0c12 += __shfl_xor_sync(0xffffffffu, s0c12, o);
            s1hd0 += __shfl_xor_sync(0xffffffffu, s1hd0, o);
            s1hd1 += __shfl_xor_sync(0xffffffffu, s1hd1, o);
            s1c00 += __shfl_xor_sync(0xffffffffu, s1c00, o);
            s1c01 += __shfl_xor_sync(0xffffffffu, s1c01, o);
            s1c02 += __shfl_xor_sync(0xffffffffu, s1c02, o);
            s1c10 += __shfl_xor_sync(0xffffffffu, s1c10, o);
            s1c11 += __shfl_xor_sync(0xffffffffu, s1c11, o);
            s1c12 += __shfl_xor_sync(0xffffffffu, s1c12, o);
        }
        if ((lane & 3) == 0) {
            float* dst = ch ? sHB : sHA;
            int row = qw*32 + (lane >> 2);
            *(float4*)(dst + row*4)      = make_float4(s0hd0, s0c00, s0c01, s0c02);
            *(float4*)(dst + (row+8)*4)  = make_float4(s0hd1, s0c10, s0c11, s0c12);
            *(float4*)(dst + (row+16)*4) = make_float4(s1hd0, s1c00, s1c01, s1c02);
            *(float4*)(dst + (row+24)*4) = make_float4(s1hd1, s1c10, s1c11, s1c12);
        }
        __syncthreads();   // heads ready; GEMM done -> A tile is dead

        // ======== BALANCED SPECIALIZED TAIL ========
        const int rn = r + G;
        if (wid < 4) {
            // warps 0-3: FE share for the next ray immediately
            if (rn < NRAYS) front_end(rn, p ^ 1);
        } else {
            // warps 4-7: epilogue for ray r (threads t = 0..127), then FE share
            const int t = tid - 128;
            const int ew = wid - 4;
            const float* rs = sRAY + p*8;
            float e_tfar_c = rs[0];
            float e_dnorm = rs[1];
            float edx = rs[3], edy = rs[4], edz = rs[5];

            float4 ha = *(const float4*)(sHA + t*4);
            float4 hb = *(const float4*)(sHB + t*4);
            float accd = ha.x + hb.x;
            float ac0  = ha.y + hb.y;
            float ac1  = ha.z + hb.z;
            float ac2  = ha.w + hb.w;

            float inv_n = 1.0f / e_dnorm;
            float Ysh[16];
            sh3(edx*inv_n, edy*inv_n, edz*inv_n, Ysh);
            #pragma unroll
            for (int q = 0; q < SHDIM; q++) {
                float wq = Ysh[q];
                ac0 = fmaf(wq, sWC[(HID + q)*3 + 0], ac0);
                ac1 = fmaf(wq, sWC[(HID + q)*3 + 1], ac1);
                ac2 = fmaf(wq, sWC[(HID + q)*3 + 2], ac2);
            }
            float zz = accd + sBC[3];
            float sig = fmaxf(zz, 0.0f) + log1pf(expf(-fabsf(zz)));
            float m = sMSK[p*128 + t];
            sig *= m;
            float mc0 = m / (1.0f + expf(-(ac0 + sBC[0])));
            float mc1 = m / (1.0f + expf(-(ac1 + sBC[1])));
            float mc2 = m / (1.0f + expf(-(ac2 + sBC[2])));
            float tsv  = sTS[p*128 + t];
            float tnxt = (t < TSAMP - 1) ? sTS[p*128 + t + 1] : (e_tfar_c * RAYEXT);
            float my_sd = sig * (tnxt - tsv) * e_dnorm;

            // inclusive scan over 128 samples within warps 4-7
            float v = my_sd;
            #pragma unroll
            for (int o = 1; o < 32; o <<= 1) {
                float n = __shfl_up_sync(0xffffffffu, v, o);
                if (lane >= o) v += n;
            }
            if (lane == 31) sWS[ew] = v;
            BAR_EPI();
            float woff = 0.0f;
            #pragma unroll
            for (int q = 0; q < 4; q++) woff += (q < ew) ? sWS[q] : 0.0f;
            float csum = v + woff;

            float wgt = expf(my_sd - csum) - expf(-csum);
            float rc0 = wgt * mc0, rc1 = wgt * mc1, rc2 = wgt * mc2;

            #pragma unroll
            for (int o = 16; o; o >>= 1) {
                rc0 += __shfl_xor_sync(0xffffffffu, rc0, o);
                rc1 += __shfl_xor_sync(0xffffffffu, rc1, o);
                rc2 += __shfl_xor_sync(0xffffffffu, rc2, o);
                wgt += __shfl_xor_sync(0xffffffffu, wgt, o);
            }
            if (lane == 0) {
                *(float4*)(sRED + ew*4) = make_float4(rc0, rc1, rc2, wgt);
            }
            BAR_EPI();
            if (t == 0) {
                float4 q0 = *(const float4*)(sRED + 0);
                float4 q1 = *(const float4*)(sRED + 4);
                float4 q2 = *(const float4*)(sRED + 8);
                float4 q3 = *(const float4*)(sRED + 12);
                float o0 = q0.x + q1.x + q2.x + q3.x;
                float o1 = q0.y + q1.y + q2.y + q3.y;
                float o2 = q0.z + q1.z + q2.z + q3.z;
                float o3 = q0.w + q1.w + q2.w + q3.w;
                bool act = (rs[2] != 0.0f);
                float4 res;
                res.x = act ? o0 : 0.0f;
                res.y = act ? o1 : 0.0f;
                res.z = act ? o2 : 0.0f;
                res.w = act ? o3 : 0.0f;
                *(float4*)(out + (size_t)r*4) = res;
            }
            // then this warp's FE share for the next ray
            if (rn < NRAYS) front_end(rn, p ^ 1);
        }
        p ^= 1;
        // loop-top __syncthreads() is the only cross-group barrier
    }
}

extern "C" void kernel_launch(void* const* d_in, const int* in_sizes, int n_in,
                              void* d_out, int out_size) {
    const float* origins = (const float*)d_in[0];
    const float* dirs    = (const float*)d_in[1];
    const float* u       = (const float*)d_in[2];
    const float* W1      = (const float*)d_in[3];
    const float* b1      = (const float*)d_in[4];
    const float* W2      = (const float*)d_in[5];
    const float* b2      = (const float*)d_in[6];
    const float* Wd      = (const float*)d_in[7];
    const float* bd      = (const float*)d_in[8];
    const float* Wc      = (const float*)d_in[9];
    const float* bc      = (const float*)d_in[10];
    float* out = (float*)d_out;

    int dev = 0, nsm = 148;
    cudaGetDevice(&dev);
    cudaDeviceGetAttribute(&nsm, cudaDevAttrMultiProcessorCount, dev);

    cudaFuncSetAttribute(radiance_kernel,
                         cudaFuncAttributeMaxDynamicSharedMemorySize, SMEM_BYTES);
    radiance_kernel<<<nsm * 2, NTHREADS, SMEM_BYTES>>>(
        origins, dirs, u, W1, b1, W2, b2, Wd, bd, Wc, bc, out);
}

// round 16
// speedup vs baseline: 1.3701x; 1.0389x over previous
#include <cuda_runtime.h>
#include <cuda_fp16.h>
#include <cstdint>
#include <math.h>

// Problem constants
#define NRAYS   8192
#define TSAMP   128
#define HID     128
#define SHDIM   16
#define RAYEXT  10.0f
#define NTHREADS 256

// ---------------- warp-level tensor-core helpers ----------------
__device__ __forceinline__ void ldsm_x4(uint32_t* r, uint32_t addr) {
    asm volatile("ldmatrix.sync.aligned.m8n8.x4.shared.b16 {%0,%1,%2,%3}, [%4];"
        : "=r"(r[0]), "=r"(r[1]), "=r"(r[2]), "=r"(r[3]) : "r"(addr));
}
__device__ __forceinline__ void ldsm_x4_t(uint32_t* r, uint32_t addr) {
    asm volatile("ldmatrix.sync.aligned.m8n8.x4.trans.shared.b16 {%0,%1,%2,%3}, [%4];"
        : "=r"(r[0]), "=r"(r[1]), "=r"(r[2]), "=r"(r[3]) : "r"(addr));
}
__device__ __forceinline__ void mma_f16(float* d, const uint32_t* a,
                                        uint32_t b0, uint32_t b1) {
    asm volatile("mma.sync.aligned.m16n8k16.row.col.f32.f16.f16.f32 "
        "{%0,%1,%2,%3}, {%4,%5,%6,%7}, {%8,%9}, {%0,%1,%2,%3};"
        : "+f"(d[0]), "+f"(d[1]), "+f"(d[2]), "+f"(d[3])
        : "r"(a[0]), "r"(a[1]), "r"(a[2]), "r"(a[3]), "r"(b0), "r"(b1));
}
__device__ __forceinline__ uint32_t smem_u32(const void* p) {
    uint32_t a;
    asm("{ .reg .u64 t; cvta.to.shared.u64 t, %1; cvt.u32.u64 %0, t; }"
        : "=r"(a) : "l"(p));
    return a;
}
__device__ __forceinline__ uint32_t pack_h2(__half a, __half b) {
    __half2 t = __halves2half2(a, b);
    return *reinterpret_cast<uint32_t*>(&t);
}
#define BAR_EPI() asm volatile("bar.sync 1, 128;" ::: "memory")

// ---------------- SMEM layout (per CTA) ----------------
#define TSTRIDE  272
#define OFF_A    0              // fp16 A tile, 128 * 272 = 34816
#define OFF_B    34816          // fp16 B tile, 128 * 272 = 34816
#define OFF_F    69632
// float-region offsets (in floats)
#define F_W1   0       // 384
#define F_B1   384     // 128
#define F_B2   512     // 128
#define F_WD   640     // 128
#define F_WC   768     // 432
#define F_BC   1200    // 4 (bc0,bc1,bc2,bd)
#define F_TS   1216    // 2 x 128
#define F_MSK  1472    // 2 x 128
#define F_WS   1728    // 8
#define F_RED  1744    // 16
#define F_RAY  1760    // 2 x 8
#define F_HA   1776    // 128*4 (heads, col-half 0)
#define F_HB   2288    // 128*4 (heads, col-half 1)
#define F_TOTAL 2800
#define SMEM_BYTES (OFF_F + F_TOTAL * 4)

__device__ __forceinline__ void sh3(float x, float y, float z, float* Y) {
    float x2 = x*x, y2 = y*y, z2 = z*z;
    float xy = x*y, yz = y*z, xz = x*z;
    Y[0]  = 0.282094791773878f;
    Y[1]  = -0.48860251190292f * y;
    Y[2]  = 0.48860251190292f * z;
    Y[3]  = -0.48860251190292f * x;
    Y[4]  = 1.0925484305920792f * xy;
    Y[5]  = -1.0925484305920792f * yz;
    Y[6]  = 0.94617469575756f * z2 - 0.31539156525252f;
    Y[7]  = -1.0925484305920792f * xz;
    Y[8]  = 0.5462742152960396f * (x2 - y2);
    Y[9]  = 0.5900435899266435f * y * (-3.0f * x2 + y2);
    Y[10] = 2.8906114426405538f * xy * z;
    Y[11] = 0.4570457994644658f * y * (1.0f - 5.0f * z2);
    Y[12] = 0.3731763325901154f * z * (5.0f * z2 - 3.0f);
    Y[13] = 0.4570457994644658f * x * (1.0f - 5.0f * z2);
    Y[14] = 1.445305721320277f * z * (x2 - y2);
    Y[15] = 0.5900435899266435f * x * (-x2 + 3.0f * y2);
}

__global__ __launch_bounds__(NTHREADS, 2)
void radiance_kernel(const float* __restrict__ origins,
                     const float* __restrict__ dirs,
                     const float* __restrict__ u,
                     const float* __restrict__ W1,
                     const float* __restrict__ b1,
                     const float* __restrict__ W2,
                     const float* __restrict__ b2,
                     const float* __restrict__ Wd,
                     const float* __restrict__ bd,
                     const float* __restrict__ Wc,
                     const float* __restrict__ bc,
                     float* __restrict__ out)
{
    extern __shared__ char smc[];
    float* sf   = (float*)(smc + OFF_F);
    float* sW1  = sf + F_W1;
    float* sB1  = sf + F_B1;
    float* sB2  = sf + F_B2;
    float* sWD  = sf + F_WD;
    float* sWC  = sf + F_WC;
    float* sBC  = sf + F_BC;
    float* sTS  = sf + F_TS;
    float* sMSK = sf + F_MSK;
    float* sWS  = sf + F_WS;
    float* sRED = sf + F_RED;
    float* sRAY = sf + F_RAY;
    float* sHA  = sf + F_HA;
    float* sHB  = sf + F_HB;

    const uint32_t sbase = smem_u32(smc);
    const int tid  = threadIdx.x;
    const int wid  = tid >> 5;
    const int lane = tid & 31;

    // ================= one-time staging (persistent CTA) =================
    for (int i = tid; i < 384; i += NTHREADS) sW1[i] = W1[i];
    if (tid < 128) {
        sB1[tid] = b1[tid];
        sB2[tid] = b2[tid];
        sWD[tid] = Wd[tid];
    }
    for (int i = tid; i < 432; i += NTHREADS) sWC[i] = Wc[i];
    if (tid < 3) sBC[tid] = bc[tid];
    if (tid == 3) sBC[3] = bd[0];

    // W2 -> B fp16 [k][n] (native layout, coalesced; one static rounding)
    {
        #pragma unroll
        for (int g = 0; g < 16; g++) {
            int idx4 = g * NTHREADS + tid;     // 0..4095 (float4 index)
            int k    = idx4 >> 5;              // 0..127
            int n4   = (idx4 & 31) << 2;       // 0..124
            float4 v = __ldg((const float4*)W2 + idx4);
            uint32_t p0 = pack_h2(__float2half(v.x), __float2half(v.y));
            uint32_t p1 = pack_h2(__float2half(v.z), __float2half(v.w));
            uint32_t off = (uint32_t)(k * TSTRIDE + n4 * 2);
            *(uint2*)(smc + OFF_B + off) = make_uint2(p0, p1);
        }
    }
    __syncthreads();

    // GEMM addressing: warp w owns rows [32*(w>>1), +32) (two 16-row slabs)
    // and col half 64*(w&1).
    const int qw = wid >> 1;           // row block 0..3
    const int ch = wid & 1;            // col half 0/1
    const uint32_t aBase0 = sbase + OFF_A
        + (uint32_t)((qw*32 + (lane & 15)) * TSTRIDE + (lane >> 4) * 16);
    const uint32_t aBase1 = aBase0 + (uint32_t)(16 * TSTRIDE);
    const int gg = lane >> 3, ii = lane & 7;
    const uint32_t bRow = (uint32_t)(((gg & 1)*8 + ii) * TSTRIDE + (gg >> 1) * 16);
    const uint32_t bBase = sbase + OFF_B + bRow + (uint32_t)(ch * 128);

    const int G = gridDim.x;

    // ---- front-end executed by warps 0-3 only: whole ray, 2 rows per lane ----
    auto front_end = [&](int ray, int buf) {
        const float ox = __ldg(origins + 3*ray + 0);
        const float oy = __ldg(origins + 3*ray + 1);
        const float oz = __ldg(origins + 3*ray + 2);
        const float dx = __ldg(dirs + 3*ray + 0);
        const float dy = __ldg(dirs + 3*ray + 1);
        const float dz = __ldg(dirs + 3*ray + 2);

        float i0 = 1.0f/dx, i1 = 1.0f/dy, i2 = 1.0f/dz;
        float a0 = (-1.0f - ox)*i0, b0 = (1.0f - ox)*i0;
        float a1 = (-1.0f - oy)*i1, b1_ = (1.0f - oy)*i1;
        float a2 = (-1.0f - oz)*i2, b2_ = (1.0f - oz)*i2;
        float mn0 = fminf(a0,b0), mx0 = fmaxf(a0,b0);
        float mn1 = fminf(a1,b1_), mx1 = fmaxf(a1,b1_);
        float mn2 = fminf(a2,b2_), mx2 = fmaxf(a2,b2_);
        float tnear = fmaxf(fmaxf(fmaxf(mn0, mn1), mn2), 0.0f);
        float tfar  = fminf(fminf(mx0, mx1), mx2);
        float activef = (tfar > tnear) ? 1.0f : 0.0f;
        float tfar_c = fmaxf(tfar, tnear + 1e-3f);
        float dnorm = sqrtf(dx*dx + dy*dy + dz*dz);

        if (tid == 0) {
            float* rs = sRAY + buf*8;
            rs[0] = tfar_c; rs[1] = dnorm; rs[2] = activef;
            rs[3] = dx; rs[4] = dy; rs[5] = dz;
        }

        const int j0 = (lane >> 4) * 64;
        #pragma unroll
        for (int rr = 0; rr < 2; rr++) {
            int row = wid*32 + (lane & 15) + rr*16;
            float uu = __ldg(u + ray*TSAMP + row);
            float frac = ((float)row + uu) * (1.0f/(float)TSAMP);
            float ts = tnear + (tfar_c - tnear) * frac;
            float px = ox + dx*ts, py = oy + dy*ts, pz = oz + dz*ts;
            bool inb = (fabsf(px) <= 1.0f) && (fabsf(py) <= 1.0f) && (fabsf(pz) <= 1.0f);
            sTS[buf*128 + row] = ts;
            sMSK[buf*128 + row] = (inb && activef != 0.0f) ? 1.0f : 0.0f;

            const uint32_t abase = (uint32_t)(OFF_A + row * TSTRIDE);
            #pragma unroll
            for (int g = 0; g < 8; g++) {
                uint32_t hp[4];
                #pragma unroll
                for (int i = 0; i < 8; i += 4) {
                    int j = j0 + g*8 + i;
                    float4 wa = *(const float4*)(sW1 + j);
                    float4 wb = *(const float4*)(sW1 + 128 + j);
                    float4 wc = *(const float4*)(sW1 + 256 + j);
                    float4 bb = *(const float4*)(sB1 + j);
                    float v0 = fmaxf(fmaf(px, wa.x, fmaf(py, wb.x, fmaf(pz, wc.x, bb.x))), 0.0f);
                    float v1 = fmaxf(fmaf(px, wa.y, fmaf(py, wb.y, fmaf(pz, wc.y, bb.y))), 0.0f);
                    float v2 = fmaxf(fmaf(px, wa.z, fmaf(py, wb.z, fmaf(pz, wc.z, bb.z))), 0.0f);
                    float v3 = fmaxf(fmaf(px, wa.w, fmaf(py, wb.w, fmaf(pz, wc.w, bb.w))), 0.0f);
                    hp[(i >> 1)]     = pack_h2(__float2half(v0), __float2half(v1));
                    hp[(i >> 1) + 1] = pack_h2(__float2half(v2), __float2half(v3));
                }
                *(uint4*)(smc + abase + (uint32_t)((j0 + g*8) * 2)) =
                    make_uint4(hp[0], hp[1], hp[2], hp[3]);
            }
        }
    };

    // prologue: warps 0-3 fill A + TS/MSK/RAY buffer 0 for the first ray
    if (wid < 4) front_end(blockIdx.x, 0);

    int p = 0;
    // ================= persistent loop: 1 ray/iter, warp-specialized tail ======
    for (int r = blockIdx.x; r < NRAYS; r += G) {
        __syncthreads();   // A, TS/MSK/RAY[p] ready

        // ---------- GEMM: 32 rows x 64 cols per warp ----------
        float acc0[8][4], acc1[8][4];
        #pragma unroll
        for (int j = 0; j < 8; j++)
            #pragma unroll
            for (int q = 0; q < 4; q++) { acc0[j][q] = 0.0f; acc1[j][q] = 0.0f; }

        #pragma unroll
        for (int s = 0; s < 8; s++) {
            uint32_t ah0[4], ah1[4];
            ldsm_x4(ah0, aBase0 + s*32);
            ldsm_x4(ah1, aBase1 + s*32);
            #pragma unroll
            for (int jp = 0; jp < 4; jp++) {
                uint32_t bh[4];
                ldsm_x4_t(bh, bBase + s*(16*TSTRIDE) + jp*32);
                mma_f16(acc0[2*jp],     ah0, bh[0], bh[1]);
                mma_f16(acc0[2*jp + 1], ah0, bh[2], bh[3]);
                mma_f16(acc1[2*jp],     ah1, bh[0], bh[1]);
                mma_f16(acc1[2*jp + 1], ah1, bh[2], bh[3]);
            }
        }

        // ---------- fused heads, both slabs in one pass ----------
        float s0hd0 = 0.0f, s0hd1 = 0.0f, s0c00 = 0.0f, s0c01 = 0.0f, s0c02 = 0.0f;
        float s0c10 = 0.0f, s0c11 = 0.0f, s0c12 = 0.0f;
        float s1hd0 = 0.0f, s1hd1 = 0.0f, s1c00 = 0.0f, s1c01 = 0.0f, s1c02 = 0.0f;
        float s1c10 = 0.0f, s1c11 = 0.0f, s1c12 = 0.0f;
        const int cbase = ch * 64 + (lane & 3) * 2;
        #pragma unroll
        for (int j = 0; j < 8; j++) {
            int c = cbase + j*8;
            float2 b2v = *(const float2*)(sB2 + c);
            float2 wdv = *(const float2*)(sWD + c);
            float2 wA = *(const float2*)(sWC + 3*c);
            float2 wB = *(const float2*)(sWC + 3*c + 2);
            float2 wC = *(const float2*)(sWC + 3*c + 4);
            float w0x = wA.x, w0y = wA.y, w0z = wB.x;
            float w1x = wB.y, w1y = wC.x, w1z = wC.y;

            float h00 = fmaxf(acc0[j][0] + b2v.x, 0.0f);
            float h01 = fmaxf(acc0[j][1] + b2v.y, 0.0f);
            float h80 = fmaxf(acc0[j][2] + b2v.x, 0.0f);
            float h81 = fmaxf(acc0[j][3] + b2v.y, 0.0f);
            s0hd0 = fmaf(h00, wdv.x, fmaf(h01, wdv.y, s0hd0));
            s0hd1 = fmaf(h80, wdv.x, fmaf(h81, wdv.y, s0hd1));
            s0c00 = fmaf(h00, w0x, fmaf(h01, w1x, s0c00));
            s0c01 = fmaf(h00, w0y, fmaf(h01, w1y, s0c01));
            s0c02 = fmaf(h00, w0z, fmaf(h01, w1z, s0c02));
            s0c10 = fmaf(h80, w0x, fmaf(h81, w1x, s0c10));
            s0c11 = fmaf(h80, w0y, fmaf(h81, w1y, s0c11));
            s0c12 = fmaf(h80, w0z, fmaf(h81, w1z, s0c12));

            float g00 = fmaxf(acc1[j][0] + b2v.x, 0.0f);
            float g01 = fmaxf(acc1[j][1] + b2v.y, 0.0f);
            float g80 = fmaxf(acc1[j][2] + b2v.x, 0.0f);
            float g81 = fmaxf(acc1[j][3] + b2v.y, 0.0f);
            s1hd0 = fmaf(g00, wdv.x, fmaf(g01, wdv.y, s1hd0));
            s1hd1 = fmaf(g80, wdv.x, fmaf(g81, wdv.y, s1hd1));
            s1c00 = fmaf(g00, w0x, fmaf(g01, w1x, s1c00));
            s1c01 = fmaf(g00, w0y, fmaf(g01, w1y, s1c01));
            s1c02 = fmaf(g00, w0z, fmaf(g01, w1z, s1c02));
            s1c10 = fmaf(g80, w0x, fmaf(g81, w1x, s1c10));
            s1c11 = fmaf(g80, w0y, fmaf(g81, w1y, s1c11));
            s1c12 = fmaf(g80, w0z, fmaf(g81, w1z, s1c12));
        }

        #pragma unroll
        for (int o = 1; o <= 2; o <<= 1) {
            s0hd0 += __shfl_xor_sync(0xffffffffu, s0hd0, o);
            s0hd1 += __shfl_xor_sync(0xffffffffu, s0hd1, o);
            s0c00 += __shfl_xor_sync(0xffffffffu, s0c00, o);
            s0c01 += __shfl_xor_sync(0xffffffffu, s0c01, o);
            s0c02 += __shfl_xor_sync(0xffffffffu, s0c02, o);
            s0c10 += __shfl_xor_sync(0xffffffffu, s0c10, o);
            s0c11 += __shfl_xor_sync(0xffffffffu, s0c11, o);
            s0c12 += __shfl_xor_sync(0xffffffffu, s0c12, o);
            s1hd0 += __shfl_xor_sync(0xffffffffu, s1hd0, o);
            s1hd1 += __shfl_xor_sync(0xffffffffu, s1hd1, o);
            s1c00 += __shfl_xor_sync(0xffffffffu, s1c00, o);
            s1c01 += __shfl_xor_sync(0xffffffffu, s1c01, o);
            s1c02 += __shfl_xor_sync(0xffffffffu, s1c02, o);
            s1c10 += __shfl_xor_sync(0xffffffffu, s1c10, o);
            s1c11 += __shfl_xor_sync(0xffffffffu, s1c11, o);
            s1c12 += __shfl_xor_sync(0xffffffffu, s1c12, o);
        }
        if ((lane & 3) == 0) {
            float* dst = ch ? sHB : sHA;
            int row = qw*32 + (lane >> 2);
            *(float4*)(dst + row*4)      = make_float4(s0hd0, s0c00, s0c01, s0c02);
            *(float4*)(dst + (row+8)*4)  = make_float4(s0hd1, s0c10, s0c11, s0c12);
            *(float4*)(dst + (row+16)*4) = make_float4(s1hd0, s1c00, s1c01, s1c02);
            *(float4*)(dst + (row+24)*4) = make_float4(s1hd1, s1c10, s1c11, s1c12);
        }
        __syncthreads();   // heads ready; GEMM done -> A tile is dead

        // ======== WARP-SPECIALIZED TAIL ========
        if (wid < 4) {
            // warps 0-3: front-end for the next ray (overwrites A, fills buf p^1)
            int rn = r + G;
            if (rn < NRAYS) front_end(rn, p ^ 1);
        } else {
            // warps 4-7: epilogue for ray r from buffer p (threads t = 0..127)
            const int t = tid - 128;
            const int ew = wid - 4;
            const float* rs = sRAY + p*8;
            float e_tfar_c = rs[0];
            float e_dnorm = rs[1];
            float edx = rs[3], edy = rs[4], edz = rs[5];

            float4 ha = *(const float4*)(sHA + t*4);
            float4 hb = *(const float4*)(sHB + t*4);
            float accd = ha.x + hb.x;
            float ac0  = ha.y + hb.y;
            float ac1  = ha.z + hb.z;
            float ac2  = ha.w + hb.w;

            float inv_n = 1.0f / e_dnorm;
            float Ysh[16];
            sh3(edx*inv_n, edy*inv_n, edz*inv_n, Ysh);
            #pragma unroll
            for (int q = 0; q < SHDIM; q++) {
                float wq = Ysh[q];
                ac0 = fmaf(wq, sWC[(HID + q)*3 + 0], ac0);
                ac1 = fmaf(wq, sWC[(HID + q)*3 + 1], ac1);
                ac2 = fmaf(wq, sWC[(HID + q)*3 + 2], ac2);
            }
            // fast-math transcendentals (error ~1e-7 rel; budget is 1e-3)
            float zz = accd + sBC[3];
            float sig = fmaxf(zz, 0.0f) + __logf(1.0f + __expf(-fabsf(zz)));
            float m = sMSK[p*128 + t];
            sig *= m;
            float mc0 = __fdividef(m, 1.0f + __expf(-(ac0 + sBC[0])));
            float mc1 = __fdividef(m, 1.0f + __expf(-(ac1 + sBC[1])));
            float mc2 = __fdividef(m, 1.0f + __expf(-(ac2 + sBC[2])));
            float tsv  = sTS[p*128 + t];
            float tnxt = (t < TSAMP - 1) ? sTS[p*128 + t + 1] : (e_tfar_c * RAYEXT);
            float my_sd = sig * (tnxt - tsv) * e_dnorm;

            // inclusive scan over 128 samples within warps 4-7
            float v = my_sd;
            #pragma unroll
            for (int o = 1; o < 32; o <<= 1) {
                float n = __shfl_up_sync(0xffffffffu, v, o);
                if (lane >= o) v += n;
            }
            if (lane == 31) sWS[ew] = v;
            BAR_EPI();
            float woff = 0.0f;
            #pragma unroll
            for (int q = 0; q < 4; q++) woff += (q < ew) ? sWS[q] : 0.0f;
            float csum = v + woff;

            float wgt = __expf(my_sd - csum) - __expf(-csum);
            float rc0 = wgt * mc0, rc1 = wgt * mc1, rc2 = wgt * mc2;

            #pragma unroll
            for (int o = 16; o; o >>= 1) {
                rc0 += __shfl_xor_sync(0xffffffffu, rc0, o);
                rc1 += __shfl_xor_sync(0xffffffffu, rc1, o);
                rc2 += __shfl_xor_sync(0xffffffffu, rc2, o);
                wgt += __shfl_xor_sync(0xffffffffu, wgt, o);
            }
            if (lane == 0) {
                *(float4*)(sRED + ew*4) = make_float4(rc0, rc1, rc2, wgt);
            }
            BAR_EPI();
            if (t == 0) {
                float4 q0 = *(const float4*)(sRED + 0);
                float4 q1 = *(const float4*)(sRED + 4);
                float4 q2 = *(const float4*)(sRED + 8);
                float4 q3 = *(const float4*)(sRED + 12);
                float o0 = q0.x + q1.x + q2.x + q3.x;
                float o1 = q0.y + q1.y + q2.y + q3.y;
                float o2 = q0.z + q1.z + q2.z + q3.z;
                float o3 = q0.w + q1.w + q2.w + q3.w;
                bool act = (rs[2] != 0.0f);
                float4 res;
                res.x = act ? o0 : 0.0f;
                res.y = act ? o1 : 0.0f;
                res.z = act ? o2 : 0.0f;
                res.w = act ? o3 : 0.0f;
                *(float4*)(out + (size_t)r*4) = res;
            }
        }
        p ^= 1;
        // loop-top __syncthreads() is the only cross-group barrier
    }
}

extern "C" void kernel_launch(void* const* d_in, const int* in_sizes, int n_in,
                              void* d_out, int out_size) {
    const float* origins = (const float*)d_in[0];
    const float* dirs    = (const float*)d_in[1];
    const float* u       = (const float*)d_in[2];
    const float* W1      = (const float*)d_in[3];
    const float* b1      = (const float*)d_in[4];
    const float* W2      = (const float*)d_in[5];
    const float* b2      = (const float*)d_in[6];
    const float* Wd      = (const float*)d_in[7];
    const float* bd      = (const float*)d_in[8];
    const float* Wc      = (const float*)d_in[9];
    const float* bc      = (const float*)d_in[10];
    float* out = (float*)d_out;

    int dev = 0, nsm = 148;
    cudaGetDevice(&dev);
    cudaDeviceGetAttribute(&nsm, cudaDevAttrMultiProcessorCount, dev);

    cudaFuncSetAttribute(radiance_kernel,
                         cudaFuncAttributeMaxDynamicSharedMemorySize, SMEM_BYTES);
    radiance_kernel<<<nsm * 2, NTHREADS, SMEM_BYTES>>>(
        origins, dirs, u, W1, b1, W2, b2, Wd, bd, Wc, bc, out);
}